// round 14
// baseline (speedup 1.0000x reference)
#include <cuda_runtime.h>
#include <cuda_fp16.h>
#include <cstdint>
#include <math.h>

// Attention_89627377533069 — FA2, fp16 mma.m16n8k16, f32 accum, 3-stage mbarrier ring.
// memory [8,1024,2048] f32 (K|V), query [8,1024,1024] f32, seq_mask [8,1024] i32, b [1] f32
// out [8,1024,1024] f32. Scalar bias b is softmax-shift-invariant -> ignored (exact).
//
// Kernel 1 converts inputs once to fp16 (RNE) into __device__ scratch, head-major,
// with log2(e) folded into Q's softmax scale (softmax computed in exp2 domain).
// Kernel 2: no __syncthreads in the mainloop — per-stage full/empty mbarriers let
// the 4 warps drift out of phase so MMA / LDSM / MUFU phases overlap across warps.

#define B_      8
#define S_      1024
#define H_      8
#define D_      128
#define UNITS_  1024
#define BM      64
#define BN      64
#define NTHREAD 128
#define NITER   (S_ / BN)    // 16
#define STAGES  3

// fp16 scratch, head-major [b*8+h][s][d]
__device__ __half g_Qh[B_ * H_ * S_ * D_];
__device__ __half g_Kh[B_ * H_ * S_ * D_];
__device__ __half g_Vh[B_ * H_ * S_ * D_];

// smem: per stage K tile then V tile, rows of 136 halfs (272B pitch; 272%128=16 ->
// conflict-free ldmatrix), 64 rows each.
#define KPITCH_B  272
#define TILE_B    17408u                    // 64 * 272
#define STG_B     34816u                    // K + V per stage
#define MOFF(s)   (3 * STG_B + (uint32_t)(s) * 256u)        // 104448 + s*256
#define MBF(s)    (3 * STG_B + 768u + (uint32_t)(s) * 8u)   // full barriers
#define MBE(s)    (3 * STG_B + 792u + (uint32_t)(s) * 8u)   // empty barriers
#define SMEM_BYTES (3 * STG_B + 1024u)      // 105472 -> 2 CTAs/SM

__device__ __forceinline__ uint32_t h2u(__half2 h) {
    union { __half2 h; uint32_t u; } cvt;
    cvt.h = h;
    return cvt.u;
}

__device__ __forceinline__ void mma16(float* c, const uint32_t* a, uint32_t b0, uint32_t b1) {
    asm volatile(
        "mma.sync.aligned.m16n8k16.row.col.f32.f16.f16.f32 "
        "{%0,%1,%2,%3}, {%4,%5,%6,%7}, {%8,%9}, {%0,%1,%2,%3};\n"
        : "+f"(c[0]), "+f"(c[1]), "+f"(c[2]), "+f"(c[3])
        : "r"(a[0]), "r"(a[1]), "r"(a[2]), "r"(a[3]), "r"(b0), "r"(b1));
}

__device__ __forceinline__ void ldsm4(uint32_t& r0, uint32_t& r1, uint32_t& r2, uint32_t& r3,
                                      uint32_t addr) {
    asm volatile("ldmatrix.sync.aligned.m8n8.x4.shared.b16 {%0,%1,%2,%3}, [%4];\n"
                 : "=r"(r0), "=r"(r1), "=r"(r2), "=r"(r3) : "r"(addr) : "memory");
}
__device__ __forceinline__ void ldsm4t(uint32_t& r0, uint32_t& r1, uint32_t& r2, uint32_t& r3,
                                       uint32_t addr) {
    asm volatile("ldmatrix.sync.aligned.m8n8.x4.trans.shared.b16 {%0,%1,%2,%3}, [%4];\n"
                 : "=r"(r0), "=r"(r1), "=r"(r2), "=r"(r3) : "r"(addr) : "memory");
}

__device__ __forceinline__ void cp16(uint32_t s, const void* g) {
    asm volatile("cp.async.ca.shared.global [%0], [%1], 16;\n" :: "r"(s), "l"(g));
}
__device__ __forceinline__ void cp4(uint32_t s, const void* g) {
    asm volatile("cp.async.ca.shared.global [%0], [%1], 4;\n" :: "r"(s), "l"(g));
}

__device__ __forceinline__ void mbar_init(uint32_t m, uint32_t c) {
    asm volatile("mbarrier.init.shared.b64 [%0], %1;" :: "r"(m), "r"(c) : "memory");
}
__device__ __forceinline__ void mbar_arrive(uint32_t m) {
    asm volatile("mbarrier.arrive.release.cta.shared::cta.b64 _, [%0];" :: "r"(m) : "memory");
}
// arm full[s]: fires one arrive when all prior cp.async of this thread complete
__device__ __forceinline__ void cpasync_mbar(uint32_t m) {
    asm volatile("cp.async.mbarrier.arrive.noinc.shared::cta.b64 [%0];" :: "r"(m) : "memory");
}
__device__ __forceinline__ void mbar_wait(uint32_t m, uint32_t p) {
    asm volatile(
        "{\n\t.reg .pred P;\n\t"
        "W%=:\n\t"
        "mbarrier.try_wait.parity.acquire.cta.shared::cta.b64 P, [%0], %1, 0x989680;\n\t"
        "@!P bra.uni W%=;\n\t}"
        :: "r"(m), "r"(p) : "memory");
}

// ---------------- convert kernel: f32 -> fp16 scratch (head-major) ----------------
__global__ void __launch_bounds__(256, 4)
convert_kernel(const float* __restrict__ memory, const float* __restrict__ query)
{
    const int idx = blockIdx.x * 256 + threadIdx.x;   // 0 .. 1048575
    const int d0 = (idx & 15) * 8;
    const int s  = (idx >> 4) & 1023;
    const int h  = (idx >> 14) & 7;
    const int b  = idx >> 17;
    // 1/sqrt(128) * log2(e): softmax evaluated with exp2
    const float scale = 0.08838834764831845f * 1.4426950408889634f;

    const size_t dst = (((size_t)(b * 8 + h) * S_) + s) * D_ + d0;
    const float* qp = query  + ((size_t)b * S_ + s) * UNITS_ + h * D_ + d0;
    const float* kp = memory + ((size_t)b * S_ + s) * 2048   + h * D_ + d0;
    const float* vp = kp + UNITS_;

    float4 a0 = ((const float4*)qp)[0], a1 = ((const float4*)qp)[1];
    uint4 q;
    q.x = h2u(__floats2half2_rn(a0.x * scale, a0.y * scale));
    q.y = h2u(__floats2half2_rn(a0.z * scale, a0.w * scale));
    q.z = h2u(__floats2half2_rn(a1.x * scale, a1.y * scale));
    q.w = h2u(__floats2half2_rn(a1.z * scale, a1.w * scale));
    *(uint4*)(g_Qh + dst) = q;

    a0 = ((const float4*)kp)[0]; a1 = ((const float4*)kp)[1];
    q.x = h2u(__floats2half2_rn(a0.x, a0.y));
    q.y = h2u(__floats2half2_rn(a0.z, a0.w));
    q.z = h2u(__floats2half2_rn(a1.x, a1.y));
    q.w = h2u(__floats2half2_rn(a1.z, a1.w));
    *(uint4*)(g_Kh + dst) = q;

    a0 = ((const float4*)vp)[0]; a1 = ((const float4*)vp)[1];
    q.x = h2u(__floats2half2_rn(a0.x, a0.y));
    q.y = h2u(__floats2half2_rn(a0.z, a0.w));
    q.z = h2u(__floats2half2_rn(a1.x, a1.y));
    q.w = h2u(__floats2half2_rn(a1.z, a1.w));
    *(uint4*)(g_Vh + dst) = q;
}

// ---------------- attention kernel ----------------
__global__ void __launch_bounds__(NTHREAD, 2)
attn_fa2_fp16_kernel(const int* __restrict__ seq_mask, float* __restrict__ out)
{
    extern __shared__ char smem[];
    const int tid  = threadIdx.x;
    const int lane = tid & 31;
    const int warp = tid >> 5;
    const int r = lane >> 2;    // fragment row group
    const int c = lane & 3;     // thread-in-group
    const int qtile = blockIdx.x;
    const int bh    = blockIdx.y;           // b*8 + h
    const int batch = bh >> 3;

    const __half* Kh = g_Kh + (size_t)bh * S_ * D_;
    const __half* Vh = g_Vh + (size_t)bh * S_ * D_;
    const int*    Mg = seq_mask + batch * S_;

    const uint32_t smb = (uint32_t)__cvta_generic_to_shared(smem);

    // ---- mbarrier init ----
    if (tid == 0) {
        #pragma unroll
        for (int s = 0; s < STAGES; s++) {
            mbar_init(smb + MBF(s), NTHREAD);  // one cp.async-arrive per thread
            mbar_init(smb + MBE(s), 4);        // one arrive per consumer warp
        }
    }
    __syncthreads();

    // ---- ldmatrix per-lane address components ----
    const int kRow = (lane & 7) + ((lane >> 4) << 3);        // key 0..15
    const int kColH = ((lane >> 3) & 1) << 3;                // d 0 or 8 (halfs)
    const uint32_t kLaneOff = (uint32_t)(kRow * KPITCH_B + kColH * 2);
    const int vRow = (lane & 7) + (((lane >> 3) & 1) << 3);  // key 0..15
    const int vColH = (lane >> 4) << 3;                      // d 0 or 8 (halfs)
    const uint32_t vLaneOff = (uint32_t)(vRow * KPITCH_B + vColH * 2) + TILE_B;

    // ---- producer: tile kt -> stage kt % 3, arms full[s] ----
    auto produce = [&](int kt) {
        const int s = kt % STAGES;
        const __half* Ks = Kh + (size_t)(kt * BN) * D_;
        const __half* Vs = Vh + (size_t)(kt * BN) * D_;
        const uint32_t base = smb + (uint32_t)s * STG_B;
        #pragma unroll
        for (int i = 0; i < 8; i++) {
            int lin = tid + i * NTHREAD;          // 0..1023
            int row = lin >> 4;                    // 0..63
            int ch  = (lin & 15) * 16;             // byte 0..240
            cp16(base + (uint32_t)(row * KPITCH_B + ch),
                 (const char*)(Ks + (size_t)row * D_) + ch);
            cp16(base + TILE_B + (uint32_t)(row * KPITCH_B + ch),
                 (const char*)(Vs + (size_t)row * D_) + ch);
        }
        if (tid < BN) cp4(smb + MOFF(s) + tid * 4, Mg + kt * BN + tid);
        cpasync_mbar(smb + MBF(s));
    };

    // ---- Q A-fragments in registers (pre-scaled fp16 from scratch) ----
    uint32_t qa[8][4];
    {
        const __half* Qp = g_Qh + ((size_t)bh * S_ + qtile * BM + warp * 16) * D_;
        #pragma unroll
        for (int kc = 0; kc < 8; kc++) {
            qa[kc][0] = *(const uint32_t*)(Qp + (size_t)r * D_       + kc * 16 + 2 * c);
            qa[kc][1] = *(const uint32_t*)(Qp + (size_t)(r + 8) * D_ + kc * 16 + 2 * c);
            qa[kc][2] = *(const uint32_t*)(Qp + (size_t)r * D_       + kc * 16 + 2 * c + 8);
            qa[kc][3] = *(const uint32_t*)(Qp + (size_t)(r + 8) * D_ + kc * 16 + 2 * c + 8);
        }
    }

    produce(0); produce(1); produce(2);

    float oacc[16][4];
    #pragma unroll
    for (int t = 0; t < 16; t++) {
        oacc[t][0] = 0.f; oacc[t][1] = 0.f; oacc[t][2] = 0.f; oacc[t][3] = 0.f;
    }
    float m0 = -INFINITY, m1 = -INFINITY;
    float l0 = 0.f, l1 = 0.f;

    for (int kt = 0; kt < NITER; kt++) {
        const int stg = kt % STAGES;
        const uint32_t fp = (uint32_t)((kt / STAGES) & 1);

        mbar_wait(smb + MBF(stg), fp);   // tile data visible (acquire)

        const int* Ms = (const int*)(smem + (size_t)MOFF(stg));
        const uint32_t kBase = smb + (uint32_t)stg * STG_B + kLaneOff;
        const uint32_t vBase = smb + (uint32_t)stg * STG_B + vLaneOff;

        // ---- S = Q K^T  ([16q x 64k] per warp) ----
        float sacc[8][4];
        #pragma unroll
        for (int j = 0; j < 8; j++) {
            sacc[j][0] = 0.f; sacc[j][1] = 0.f; sacc[j][2] = 0.f; sacc[j][3] = 0.f;
        }
        #pragma unroll
        for (int kc = 0; kc < 8; kc++) {          // d chunks of 16
            #pragma unroll
            for (int p = 0; p < 4; p++) {          // key groups of 16
                uint32_t b0, b1, b2, b3;
                ldsm4(b0, b1, b2, b3,
                      kBase + (uint32_t)(p * 16 * KPITCH_B + kc * 32));
                mma16(sacc[2 * p],     qa[kc], b0, b1);
                mma16(sacc[2 * p + 1], qa[kc], b2, b3);
            }
        }

        // ---- key mask (additive -1e30) ----
        #pragma unroll
        for (int j = 0; j < 8; j++) {
            float a0 = Ms[j * 8 + 2 * c]     ? 0.f : -1e30f;
            float a1 = Ms[j * 8 + 2 * c + 1] ? 0.f : -1e30f;
            sacc[j][0] += a0; sacc[j][2] += a0;
            sacc[j][1] += a1; sacc[j][3] += a1;
        }

        // ---- online softmax (exp2 domain; log2e folded into Q scale) ----
        float mx0 = -INFINITY, mx1 = -INFINITY;
        #pragma unroll
        for (int j = 0; j < 8; j++) {
            mx0 = fmaxf(mx0, fmaxf(sacc[j][0], sacc[j][1]));
            mx1 = fmaxf(mx1, fmaxf(sacc[j][2], sacc[j][3]));
        }
        mx0 = fmaxf(mx0, __shfl_xor_sync(0xffffffffu, mx0, 1));
        mx0 = fmaxf(mx0, __shfl_xor_sync(0xffffffffu, mx0, 2));
        mx1 = fmaxf(mx1, __shfl_xor_sync(0xffffffffu, mx1, 1));
        mx1 = fmaxf(mx1, __shfl_xor_sync(0xffffffffu, mx1, 2));

        float mn0 = fmaxf(m0, mx0), mn1 = fmaxf(m1, mx1);
        float al0 = exp2f(m0 - mn0), al1 = exp2f(m1 - mn1);
        m0 = mn0; m1 = mn1;

        // ---- P -> fp16 A-fragments directly in registers ----
        uint32_t pa[4][4];
        float rs0 = 0.f, rs1 = 0.f;
        #pragma unroll
        for (int j = 0; j < 8; j++) {
            __half2 h01 = __floats2half2_rn(exp2f(sacc[j][0] - mn0), exp2f(sacc[j][1] - mn0));
            __half2 h23 = __floats2half2_rn(exp2f(sacc[j][2] - mn1), exp2f(sacc[j][3] - mn1));
            float2 f01 = __half22float2(h01);
            float2 f23 = __half22float2(h23);
            rs0 += f01.x + f01.y;
            rs1 += f23.x + f23.y;
            pa[j >> 1][(j & 1) ? 2 : 0] = h2u(h01);
            pa[j >> 1][(j & 1) ? 3 : 1] = h2u(h23);
        }
        rs0 += __shfl_xor_sync(0xffffffffu, rs0, 1);
        rs0 += __shfl_xor_sync(0xffffffffu, rs0, 2);
        rs1 += __shfl_xor_sync(0xffffffffu, rs1, 1);
        rs1 += __shfl_xor_sync(0xffffffffu, rs1, 2);
        l0 = l0 * al0 + rs0;
        l1 = l1 * al1 + rs1;

        // ---- O rescale (warp-uniform skip when no row max moved) ----
        bool noresc = (al0 == 1.f) && (al1 == 1.f);
        if (!__all_sync(0xffffffffu, noresc)) {
            #pragma unroll
            for (int t = 0; t < 16; t++) {
                oacc[t][0] *= al0; oacc[t][1] *= al0;
                oacc[t][2] *= al1; oacc[t][3] *= al1;
            }
        }

        // ---- O += P V  (B via ldmatrix.trans on V[key][d]) ----
        #pragma unroll
        for (int kc = 0; kc < 4; kc++) {          // key chunks of 16
            #pragma unroll
            for (int dp = 0; dp < 8; dp++) {       // d pairs of 16
                uint32_t v0, v1, v2, v3;
                ldsm4t(v0, v1, v2, v3,
                       vBase + (uint32_t)(kc * 16 * KPITCH_B + dp * 32));
                mma16(oacc[2 * dp],     pa[kc], v0, v1);
                mma16(oacc[2 * dp + 1], pa[kc], v2, v3);
            }
        }

        // ---- stage consumed: release to producer; refill ----
        __syncwarp();
        if (lane == 0) mbar_arrive(smb + MBE(stg));
        if (kt + STAGES < NITER) {
            mbar_wait(smb + MBE(stg), fp);   // all 4 warps consumed
            produce(kt + STAGES);
        }
    }

    // ---- epilogue: normalize + store (f32) ----
    const float li0 = 1.f / l0;
    const float li1 = 1.f / l1;
    const int head = bh & 7;
    float* Op = out + ((size_t)batch * S_ + (size_t)qtile * BM + warp * 16) * UNITS_
              + head * D_;
    #pragma unroll
    for (int t = 0; t < 16; t++) {
        *(float2*)(Op + (size_t)r * UNITS_ + t * 8 + 2 * c) =
            make_float2(oacc[t][0] * li0, oacc[t][1] * li0);
        *(float2*)(Op + (size_t)(r + 8) * UNITS_ + t * 8 + 2 * c) =
            make_float2(oacc[t][2] * li1, oacc[t][3] * li1);
    }
}

extern "C" void kernel_launch(void* const* d_in, const int* in_sizes, int n_in,
                              void* d_out, int out_size)
{
    const float* memory = (const float*)d_in[0];
    const float* query  = (const float*)d_in[1];
    const int*   seqm   = (const int*)d_in[2];
    // d_in[3] (scalar bias b) is provably a no-op under softmax -> ignored.

    convert_kernel<<<4096, 256>>>(memory, query);

    cudaFuncSetAttribute(attn_fa2_fp16_kernel,
                         cudaFuncAttributeMaxDynamicSharedMemorySize, SMEM_BYTES);
    dim3 grid(S_ / BM, B_ * H_);
    attn_fa2_fp16_kernel<<<grid, NTHREAD, SMEM_BYTES>>>(seqm, (float*)d_out);
}

// round 15
// speedup vs baseline: 1.1859x; 1.1859x over previous
#include <cuda_runtime.h>
#include <cuda_fp16.h>
#include <cstdint>
#include <math.h>

// Attention_89627377533069 — FA2, fp16 mma.m16n8k16, f32 accum.
// memory [8,1024,2048] f32 (K|V), query [8,1024,1024] f32, seq_mask [8,1024] i32, b [1] f32
// out [8,1024,1024] f32. Scalar bias b is softmax-shift-invariant -> ignored (exact).
//
// Kernel 1 converts inputs once to fp16 (RNE) into __device__ scratch, head-major,
// with log2(e) folded into Q's scale (softmax runs in the exp2 domain).
// Kernel 2 (R12 skeleton: double buffer + one __syncthreads/iter):
//   - K via ldmatrix, V via ldmatrix.trans, P packed straight into A-fragments
//   - P row-sums (softmax denominator) computed by an extra mma against all-ones B
//   - exp evaluated as ex2.approx.f16x2 on the packed half2 fragments

#define B_      8
#define S_      1024
#define H_      8
#define D_      128
#define UNITS_  1024
#define BM      64
#define BN      64
#define NTHREAD 128
#define NITER   (S_ / BN)    // 16

// fp16 scratch, head-major [b*8+h][s][d]
__device__ __half g_Qh[B_ * H_ * S_ * D_];
__device__ __half g_Kh[B_ * H_ * S_ * D_];
__device__ __half g_Vh[B_ * H_ * S_ * D_];

// smem: K/V tiles [64 rows][136 halfs] (272B pitch; 272%128=16 -> conflict-free ldmatrix)
#define KPITCH_B  272
#define TILE_B    (BN * KPITCH_B)          // 17408
#define KOFFB(s)  ((uint32_t)(s) * TILE_B)              // 0, 17408
#define VOFFB(s)  (uint32_t)(2 * TILE_B + (s) * TILE_B) // 34816, 52224
#define MOFFB(s)  (uint32_t)(4 * TILE_B + (s) * 256)    // 69632, 69888
#define SMEM_BYTES (4 * TILE_B + 512)      // 70144 -> 2 CTAs/SM

#define ONES_H2 0x3C003C00u                 // half2(1.0, 1.0)

__device__ __forceinline__ uint32_t h2u(__half2 h) {
    union { __half2 h; uint32_t u; } cvt;
    cvt.h = h;
    return cvt.u;
}

__device__ __forceinline__ uint32_t ex2h2(uint32_t x) {
    uint32_t d;
    asm("ex2.approx.f16x2 %0, %1;" : "=r"(d) : "r"(x));
    return d;
}

__device__ __forceinline__ void mma16(float* c, const uint32_t* a, uint32_t b0, uint32_t b1) {
    asm volatile(
        "mma.sync.aligned.m16n8k16.row.col.f32.f16.f16.f32 "
        "{%0,%1,%2,%3}, {%4,%5,%6,%7}, {%8,%9}, {%0,%1,%2,%3};\n"
        : "+f"(c[0]), "+f"(c[1]), "+f"(c[2]), "+f"(c[3])
        : "r"(a[0]), "r"(a[1]), "r"(a[2]), "r"(a[3]), "r"(b0), "r"(b1));
}

__device__ __forceinline__ void ldsm4(uint32_t& r0, uint32_t& r1, uint32_t& r2, uint32_t& r3,
                                      uint32_t addr) {
    asm volatile("ldmatrix.sync.aligned.m8n8.x4.shared.b16 {%0,%1,%2,%3}, [%4];\n"
                 : "=r"(r0), "=r"(r1), "=r"(r2), "=r"(r3) : "r"(addr) : "memory");
}
__device__ __forceinline__ void ldsm4t(uint32_t& r0, uint32_t& r1, uint32_t& r2, uint32_t& r3,
                                       uint32_t addr) {
    asm volatile("ldmatrix.sync.aligned.m8n8.x4.trans.shared.b16 {%0,%1,%2,%3}, [%4];\n"
                 : "=r"(r0), "=r"(r1), "=r"(r2), "=r"(r3) : "r"(addr) : "memory");
}

__device__ __forceinline__ void cp16(uint32_t s, const void* g) {
    asm volatile("cp.async.ca.shared.global [%0], [%1], 16;\n" :: "r"(s), "l"(g));
}
__device__ __forceinline__ void cp4(uint32_t s, const void* g) {
    asm volatile("cp.async.ca.shared.global [%0], [%1], 4;\n" :: "r"(s), "l"(g));
}

// ---------------- convert kernel: f32 -> fp16 scratch (head-major) ----------------
__global__ void __launch_bounds__(256, 4)
convert_kernel(const float* __restrict__ memory, const float* __restrict__ query)
{
    const int idx = blockIdx.x * 256 + threadIdx.x;   // 0 .. 1048575
    const int d0 = (idx & 15) * 8;
    const int s  = (idx >> 4) & 1023;
    const int h  = (idx >> 14) & 7;
    const int b  = idx >> 17;
    // 1/sqrt(128) * log2(e): softmax evaluated with exp2
    const float scale = 0.08838834764831845f * 1.4426950408889634f;

    const size_t dst = (((size_t)(b * 8 + h) * S_) + s) * D_ + d0;
    const float* qp = query  + ((size_t)b * S_ + s) * UNITS_ + h * D_ + d0;
    const float* kp = memory + ((size_t)b * S_ + s) * 2048   + h * D_ + d0;
    const float* vp = kp + UNITS_;

    float4 a0 = ((const float4*)qp)[0], a1 = ((const float4*)qp)[1];
    uint4 q;
    q.x = h2u(__floats2half2_rn(a0.x * scale, a0.y * scale));
    q.y = h2u(__floats2half2_rn(a0.z * scale, a0.w * scale));
    q.z = h2u(__floats2half2_rn(a1.x * scale, a1.y * scale));
    q.w = h2u(__floats2half2_rn(a1.z * scale, a1.w * scale));
    *(uint4*)(g_Qh + dst) = q;

    a0 = ((const float4*)kp)[0]; a1 = ((const float4*)kp)[1];
    q.x = h2u(__floats2half2_rn(a0.x, a0.y));
    q.y = h2u(__floats2half2_rn(a0.z, a0.w));
    q.z = h2u(__floats2half2_rn(a1.x, a1.y));
    q.w = h2u(__floats2half2_rn(a1.z, a1.w));
    *(uint4*)(g_Kh + dst) = q;

    a0 = ((const float4*)vp)[0]; a1 = ((const float4*)vp)[1];
    q.x = h2u(__floats2half2_rn(a0.x, a0.y));
    q.y = h2u(__floats2half2_rn(a0.z, a0.w));
    q.z = h2u(__floats2half2_rn(a1.x, a1.y));
    q.w = h2u(__floats2half2_rn(a1.z, a1.w));
    *(uint4*)(g_Vh + dst) = q;
}

// ---------------- attention kernel ----------------
__global__ void __launch_bounds__(NTHREAD, 2)
attn_fa2_fp16_kernel(const int* __restrict__ seq_mask, float* __restrict__ out)
{
    extern __shared__ char smem[];
    const int tid  = threadIdx.x;
    const int warp = tid >> 5;
    const int lane = tid & 31;
    const int r = lane >> 2;    // fragment row group
    const int c = lane & 3;     // thread-in-group
    const int qtile = blockIdx.x;
    const int bh    = blockIdx.y;           // b*8 + h
    const int batch = bh >> 3;

    const __half* Kh = g_Kh + (size_t)bh * S_ * D_;
    const __half* Vh = g_Vh + (size_t)bh * S_ * D_;
    const int*    Mg = seq_mask + batch * S_;

    const uint32_t smb = (uint32_t)__cvta_generic_to_shared(smem);

    // ---- ldmatrix per-lane address components ----
    const int kRow = (lane & 7) + ((lane >> 4) << 3);        // key 0..15
    const int kColH = ((lane >> 3) & 1) << 3;                // d 0 or 8 (halfs)
    const uint32_t kLaneOff = (uint32_t)(kRow * KPITCH_B + kColH * 2);
    const int vRow = (lane & 7) + (((lane >> 3) & 1) << 3);  // key 0..15
    const int vColH = (lane >> 4) << 3;                      // d 0 or 8 (halfs)
    const uint32_t vLaneOff = (uint32_t)(vRow * KPITCH_B + vColH * 2);

    // ---- Q A-fragments in registers (pre-scaled fp16 from scratch) ----
    uint32_t qa[8][4];
    {
        const __half* Qp = g_Qh + ((size_t)bh * S_ + qtile * BM + warp * 16) * D_;
        #pragma unroll
        for (int kc = 0; kc < 8; kc++) {
            qa[kc][0] = *(const uint32_t*)(Qp + (size_t)r * D_       + kc * 16 + 2 * c);
            qa[kc][1] = *(const uint32_t*)(Qp + (size_t)(r + 8) * D_ + kc * 16 + 2 * c);
            qa[kc][2] = *(const uint32_t*)(Qp + (size_t)r * D_       + kc * 16 + 2 * c + 8);
            qa[kc][3] = *(const uint32_t*)(Qp + (size_t)(r + 8) * D_ + kc * 16 + 2 * c + 8);
        }
    }

    float oacc[16][4];
    #pragma unroll
    for (int t = 0; t < 16; t++) {
        oacc[t][0] = 0.f; oacc[t][1] = 0.f; oacc[t][2] = 0.f; oacc[t][3] = 0.f;
    }
    float m0 = -INFINITY, m1 = -INFINITY;
    float l0 = 0.f, l1 = 0.f;

    // ---- double-buffered KV tile loader (fp16, 256B rows) ----
    auto issue = [&](int stage, int kt) {
        const __half* Ks = Kh + (size_t)(kt * BN) * D_;
        const __half* Vs = Vh + (size_t)(kt * BN) * D_;
        #pragma unroll
        for (int i = 0; i < 8; i++) {
            int lin = tid + i * NTHREAD;          // 0..1023
            int row = lin >> 4;                    // 0..63
            int ch  = (lin & 15) * 16;             // byte 0..240
            cp16(smb + KOFFB(stage) + (uint32_t)(row * KPITCH_B + ch),
                 (const char*)(Ks + (size_t)row * D_) + ch);
            cp16(smb + VOFFB(stage) + (uint32_t)(row * KPITCH_B + ch),
                 (const char*)(Vs + (size_t)row * D_) + ch);
        }
        if (tid < BN)
            cp4(smb + MOFFB(stage) + tid * 4, Mg + kt * BN + tid);
        asm volatile("cp.async.commit_group;\n" ::: "memory");
    };

    issue(0, 0);

    for (int kt = 0; kt < NITER; kt++) {
        const int cur = kt & 1;

        asm volatile("cp.async.wait_group 0;\n" ::: "memory");
        __syncthreads();   // tile ready; all warps past previous iter (WAR on other stage)

        if (kt + 1 < NITER) issue(cur ^ 1, kt + 1);

        const int* Ms = (const int*)(smem + MOFFB(cur));
        const uint32_t kBase = smb + KOFFB(cur) + kLaneOff;
        const uint32_t vBase = smb + VOFFB(cur) + vLaneOff;

        // ---- S = Q K^T  ([16q x 64k] per warp) ----
        float sacc[8][4];
        #pragma unroll
        for (int j = 0; j < 8; j++) {
            sacc[j][0] = 0.f; sacc[j][1] = 0.f; sacc[j][2] = 0.f; sacc[j][3] = 0.f;
        }
        #pragma unroll
        for (int kc = 0; kc < 8; kc++) {          // d chunks of 16
            #pragma unroll
            for (int p = 0; p < 4; p++) {          // key groups of 16
                uint32_t b0, b1, b2, b3;
                ldsm4(b0, b1, b2, b3,
                      kBase + (uint32_t)(p * 16 * KPITCH_B + kc * 32));
                mma16(sacc[2 * p],     qa[kc], b0, b1);
                mma16(sacc[2 * p + 1], qa[kc], b2, b3);
            }
        }

        // ---- key mask (additive -1e30) ----
        #pragma unroll
        for (int j = 0; j < 8; j++) {
            float a0 = Ms[j * 8 + 2 * c]     ? 0.f : -1e30f;
            float a1 = Ms[j * 8 + 2 * c + 1] ? 0.f : -1e30f;
            sacc[j][0] += a0; sacc[j][2] += a0;
            sacc[j][1] += a1; sacc[j][3] += a1;
        }

        // ---- online softmax (exp2 domain) ----
        float mx0 = -INFINITY, mx1 = -INFINITY;
        #pragma unroll
        for (int j = 0; j < 8; j++) {
            mx0 = fmaxf(mx0, fmaxf(sacc[j][0], sacc[j][1]));
            mx1 = fmaxf(mx1, fmaxf(sacc[j][2], sacc[j][3]));
        }
        mx0 = fmaxf(mx0, __shfl_xor_sync(0xffffffffu, mx0, 1));
        mx0 = fmaxf(mx0, __shfl_xor_sync(0xffffffffu, mx0, 2));
        mx1 = fmaxf(mx1, __shfl_xor_sync(0xffffffffu, mx1, 1));
        mx1 = fmaxf(mx1, __shfl_xor_sync(0xffffffffu, mx1, 2));

        float mn0 = fmaxf(m0, mx0), mn1 = fmaxf(m1, mx1);
        float al0 = exp2f(m0 - mn0), al1 = exp2f(m1 - mn1);
        m0 = mn0; m1 = mn1;

        // ---- P: subtract max in f32, pack half2, exp via ex2.approx.f16x2 ----
        // pa layout per 16-key chunk: a0=(r, k=2c..), a1=(r+8), a2/a3 = +8 keys.
        uint32_t pa[4][4];
        #pragma unroll
        for (int j = 0; j < 8; j++) {
            uint32_t h01 = h2u(__floats2half2_rn(sacc[j][0] - mn0, sacc[j][1] - mn0));
            uint32_t h23 = h2u(__floats2half2_rn(sacc[j][2] - mn1, sacc[j][3] - mn1));
            pa[j >> 1][(j & 1) ? 2 : 0] = ex2h2(h01);
            pa[j >> 1][(j & 1) ? 3 : 1] = ex2h2(h23);
        }

        // ---- row sums of P via mma against all-ones B (no shuffles needed) ----
        float lacc[4] = {0.f, 0.f, 0.f, 0.f};
        #pragma unroll
        for (int kc = 0; kc < 4; kc++)
            mma16(lacc, pa[kc], ONES_H2, ONES_H2);
        l0 = l0 * al0 + lacc[0];   // every column of the ones-mma = rowsum(row r)
        l1 = l1 * al1 + lacc[2];   // rowsum(row r+8)

        // ---- O rescale (warp-uniform skip when no row max moved) ----
        bool noresc = (al0 == 1.f) && (al1 == 1.f);
        if (!__all_sync(0xffffffffu, noresc)) {
            #pragma unroll
            for (int t = 0; t < 16; t++) {
                oacc[t][0] *= al0; oacc[t][1] *= al0;
                oacc[t][2] *= al1; oacc[t][3] *= al1;
            }
        }

        // ---- O += P V  (B via ldmatrix.trans on V[key][d]) ----
        #pragma unroll
        for (int kc = 0; kc < 4; kc++) {          // key chunks of 16
            #pragma unroll
            for (int dp = 0; dp < 8; dp++) {       // d pairs of 16
                uint32_t v0, v1, v2, v3;
                ldsm4t(v0, v1, v2, v3,
                       vBase + (uint32_t)(kc * 16 * KPITCH_B + dp * 32));
                mma16(oacc[2 * dp],     pa[kc], v0, v1);
                mma16(oacc[2 * dp + 1], pa[kc], v2, v3);
            }
        }
        // next iteration's top __syncthreads guards stage reuse
    }

    // ---- epilogue: normalize + store (f32) ----
    const float li0 = 1.f / l0;
    const float li1 = 1.f / l1;
    const int head = bh & 7;
    float* Op = out + ((size_t)batch * S_ + (size_t)qtile * BM + warp * 16) * UNITS_
              + head * D_;
    #pragma unroll
    for (int t = 0; t < 16; t++) {
        *(float2*)(Op + (size_t)r * UNITS_ + t * 8 + 2 * c) =
            make_float2(oacc[t][0] * li0, oacc[t][1] * li0);
        *(float2*)(Op + (size_t)(r + 8) * UNITS_ + t * 8 + 2 * c) =
            make_float2(oacc[t][2] * li1, oacc[t][3] * li1);
    }
}

extern "C" void kernel_launch(void* const* d_in, const int* in_sizes, int n_in,
                              void* d_out, int out_size)
{
    const float* memory = (const float*)d_in[0];
    const float* query  = (const float*)d_in[1];
    const int*   seqm   = (const int*)d_in[2];
    // d_in[3] (scalar bias b) is provably a no-op under softmax -> ignored.

    convert_kernel<<<4096, 256>>>(memory, query);

    cudaFuncSetAttribute(attn_fa2_fp16_kernel,
                         cudaFuncAttributeMaxDynamicSharedMemorySize, SMEM_BYTES);
    dim3 grid(S_ / BM, B_ * H_);
    attn_fa2_fp16_kernel<<<grid, NTHREAD, SMEM_BYTES>>>(seqm, (float*)d_out);
}

// round 16
// speedup vs baseline: 1.8128x; 1.5287x over previous
#include <cuda_runtime.h>
#include <cuda_fp16.h>
#include <cstdint>
#include <math.h>

// Attention_89627377533069 — FA2 fp16 mma.m16n8k16 + masked-key compaction.
// memory [8,1024,2048] f32 (K|V), query [8,1024,1024] f32, seq_mask [8,1024] i32, b [1] f32
// out [8,1024,1024] f32. Scalar bias b is softmax-shift-invariant -> ignored (exact).
//
// Masked keys (seq_mask==0, ~50%) contribute exactly 0 to the reference output
// (exp underflow vs -1e30), and softmax is invariant under a shared K/V permutation.
// So: prefix-scan the mask, compact K/V to valid keys only, and run the KV loop
// over ~S/2 keys. Q scaled by 1/sqrt(d)*log2(e); softmax in the exp2 domain;
// P row-sums via an extra mma against all-ones B; exp via ex2.approx.f16x2.

#define B_      8
#define S_      1024
#define H_      8
#define D_      128
#define UNITS_  1024
#define BM      64
#define BN      64
#define NTHREAD 128

// fp16 scratch, head-major [b*8+h][s][d]; K/V hold compacted keys.
__device__ __half g_Qh[B_ * H_ * S_ * D_];
__device__ __half g_Kh[B_ * H_ * S_ * D_];
__device__ __half g_Vh[B_ * H_ * S_ * D_];
__device__ int    g_idx[B_ * S_];   // compacted destination per valid key
__device__ int    g_cnt[B_];        // valid-key count per batch

// smem: K/V tiles [64 rows][136 halfs] (272B pitch; 272%128=16 -> conflict-free ldmatrix)
#define KPITCH_B  272
#define TILE_B    (BN * KPITCH_B)          // 17408
#define KOFFB(s)  ((uint32_t)(s) * TILE_B)              // 0, 17408
#define VOFFB(s)  (uint32_t)(2 * TILE_B + (s) * TILE_B) // 34816, 52224
#define SMEM_BYTES (4 * TILE_B)            // 69632 -> 2 CTAs/SM

#define ONES_H2 0x3C003C00u                 // half2(1.0, 1.0)

__device__ __forceinline__ uint32_t h2u(__half2 h) {
    union { __half2 h; uint32_t u; } cvt;
    cvt.h = h;
    return cvt.u;
}

__device__ __forceinline__ uint32_t ex2h2(uint32_t x) {
    uint32_t d;
    asm("ex2.approx.f16x2 %0, %1;" : "=r"(d) : "r"(x));
    return d;
}

__device__ __forceinline__ void mma16(float* c, const uint32_t* a, uint32_t b0, uint32_t b1) {
    asm volatile(
        "mma.sync.aligned.m16n8k16.row.col.f32.f16.f16.f32 "
        "{%0,%1,%2,%3}, {%4,%5,%6,%7}, {%8,%9}, {%0,%1,%2,%3};\n"
        : "+f"(c[0]), "+f"(c[1]), "+f"(c[2]), "+f"(c[3])
        : "r"(a[0]), "r"(a[1]), "r"(a[2]), "r"(a[3]), "r"(b0), "r"(b1));
}

__device__ __forceinline__ void ldsm4(uint32_t& r0, uint32_t& r1, uint32_t& r2, uint32_t& r3,
                                      uint32_t addr) {
    asm volatile("ldmatrix.sync.aligned.m8n8.x4.shared.b16 {%0,%1,%2,%3}, [%4];\n"
                 : "=r"(r0), "=r"(r1), "=r"(r2), "=r"(r3) : "r"(addr) : "memory");
}
__device__ __forceinline__ void ldsm4t(uint32_t& r0, uint32_t& r1, uint32_t& r2, uint32_t& r3,
                                       uint32_t addr) {
    asm volatile("ldmatrix.sync.aligned.m8n8.x4.trans.shared.b16 {%0,%1,%2,%3}, [%4];\n"
                 : "=r"(r0), "=r"(r1), "=r"(r2), "=r"(r3) : "r"(addr) : "memory");
}

__device__ __forceinline__ void cp16(uint32_t s, const void* g) {
    asm volatile("cp.async.ca.shared.global [%0], [%1], 16;\n" :: "r"(s), "l"(g));
}

// ---------------- scan kernel: mask prefix-scan + pad zeroing ----------------
__global__ void __launch_bounds__(1024, 1)
scan_kernel(const int* __restrict__ seq_mask)
{
    const int b = blockIdx.x;
    const int tid = threadIdx.x;
    const int lane = tid & 31, w = tid >> 5;

    int m = seq_mask[b * S_ + tid] ? 1 : 0;
    int x = m;
    #pragma unroll
    for (int o = 1; o < 32; o <<= 1) {
        int y = __shfl_up_sync(0xffffffffu, x, o);
        if (lane >= o) x += y;
    }
    __shared__ int ws[32];
    __shared__ int cnt_s;
    if (lane == 31) ws[w] = x;
    __syncthreads();
    if (w == 0) {
        int y = ws[lane];
        #pragma unroll
        for (int o = 1; o < 32; o <<= 1) {
            int z = __shfl_up_sync(0xffffffffu, y, o);
            if (lane >= o) y += z;
        }
        ws[lane] = y;
    }
    __syncthreads();
    int incl = x + (w > 0 ? ws[w - 1] : 0);
    if (m) g_idx[b * S_ + tid] = incl - 1;
    if (tid == 1023) { cnt_s = incl; g_cnt[b] = incl; }
    __syncthreads();

    // zero compacted pad region [cnt, roundup64(cnt)) for all heads
    const int cnt = cnt_s;
    const int pad = (cnt + 63) & ~63;
    const int pairs = (pad - cnt) * 8;
    if (tid < pairs) {
        int row = cnt + (tid >> 3);
        int h = tid & 7;
        const size_t off = ((size_t)(b * 8 + h) * S_ + row) * D_;
        uint4 z = make_uint4(0, 0, 0, 0);
        uint4* kp = (uint4*)(g_Kh + off);
        uint4* vp = (uint4*)(g_Vh + off);
        #pragma unroll
        for (int i = 0; i < 16; i++) { kp[i] = z; vp[i] = z; }
    }
}

// ---------------- convert kernel: f32 -> fp16 scratch (head-major, compacted K/V) --
__global__ void __launch_bounds__(256, 4)
convert_kernel(const float* __restrict__ memory, const float* __restrict__ query,
               const int* __restrict__ seq_mask)
{
    const int idx = blockIdx.x * 256 + threadIdx.x;   // 0 .. 1048575
    const int d0 = (idx & 15) * 8;
    const int s  = (idx >> 4) & 1023;
    const int h  = (idx >> 14) & 7;
    const int b  = idx >> 17;
    // 1/sqrt(128) * log2(e): softmax evaluated with exp2
    const float scale = 0.08838834764831845f * 1.4426950408889634f;

    const float* qp = query  + ((size_t)b * S_ + s) * UNITS_ + h * D_ + d0;
    float4 a0 = ((const float4*)qp)[0], a1 = ((const float4*)qp)[1];
    uint4 q;
    q.x = h2u(__floats2half2_rn(a0.x * scale, a0.y * scale));
    q.y = h2u(__floats2half2_rn(a0.z * scale, a0.w * scale));
    q.z = h2u(__floats2half2_rn(a1.x * scale, a1.y * scale));
    q.w = h2u(__floats2half2_rn(a1.z * scale, a1.w * scale));
    *(uint4*)(g_Qh + (((size_t)(b * 8 + h) * S_) + s) * D_ + d0) = q;

    if (!seq_mask[b * S_ + s]) return;
    const int ds = g_idx[b * S_ + s];
    const size_t dst = (((size_t)(b * 8 + h) * S_) + ds) * D_ + d0;
    const float* kp = memory + ((size_t)b * S_ + s) * 2048 + h * D_ + d0;
    const float* vp = kp + UNITS_;

    a0 = ((const float4*)kp)[0]; a1 = ((const float4*)kp)[1];
    q.x = h2u(__floats2half2_rn(a0.x, a0.y));
    q.y = h2u(__floats2half2_rn(a0.z, a0.w));
    q.z = h2u(__floats2half2_rn(a1.x, a1.y));
    q.w = h2u(__floats2half2_rn(a1.z, a1.w));
    *(uint4*)(g_Kh + dst) = q;

    a0 = ((const float4*)vp)[0]; a1 = ((const float4*)vp)[1];
    q.x = h2u(__floats2half2_rn(a0.x, a0.y));
    q.y = h2u(__floats2half2_rn(a0.z, a0.w));
    q.z = h2u(__floats2half2_rn(a1.x, a1.y));
    q.w = h2u(__floats2half2_rn(a1.z, a1.w));
    *(uint4*)(g_Vh + dst) = q;
}

// ---------------- attention kernel ----------------
__global__ void __launch_bounds__(NTHREAD, 2)
attn_fa2_fp16_kernel(float* __restrict__ out)
{
    extern __shared__ char smem[];
    const int tid  = threadIdx.x;
    const int warp = tid >> 5;
    const int lane = tid & 31;
    const int r = lane >> 2;    // fragment row group
    const int c = lane & 3;     // thread-in-group
    const int qtile = blockIdx.x;
    const int bh    = blockIdx.y;           // b*8 + h
    const int batch = bh >> 3;

    const __half* Kh = g_Kh + (size_t)bh * S_ * D_;
    const __half* Vh = g_Vh + (size_t)bh * S_ * D_;
    const int cnt = g_cnt[batch];
    const int niter = (cnt + BN - 1) >> 6;   // tiles of 64 compacted keys

    const uint32_t smb = (uint32_t)__cvta_generic_to_shared(smem);

    // ---- ldmatrix per-lane address components ----
    const int kRow = (lane & 7) + ((lane >> 4) << 3);        // key 0..15
    const int kColH = ((lane >> 3) & 1) << 3;                // d 0 or 8 (halfs)
    const uint32_t kLaneOff = (uint32_t)(kRow * KPITCH_B + kColH * 2);
    const int vRow = (lane & 7) + (((lane >> 3) & 1) << 3);  // key 0..15
    const int vColH = (lane >> 4) << 3;                      // d 0 or 8 (halfs)
    const uint32_t vLaneOff = (uint32_t)(vRow * KPITCH_B + vColH * 2);

    // ---- Q A-fragments in registers (pre-scaled fp16 from scratch) ----
    uint32_t qa[8][4];
    {
        const __half* Qp = g_Qh + ((size_t)bh * S_ + qtile * BM + warp * 16) * D_;
        #pragma unroll
        for (int kc = 0; kc < 8; kc++) {
            qa[kc][0] = *(const uint32_t*)(Qp + (size_t)r * D_       + kc * 16 + 2 * c);
            qa[kc][1] = *(const uint32_t*)(Qp + (size_t)(r + 8) * D_ + kc * 16 + 2 * c);
            qa[kc][2] = *(const uint32_t*)(Qp + (size_t)r * D_       + kc * 16 + 2 * c + 8);
            qa[kc][3] = *(const uint32_t*)(Qp + (size_t)(r + 8) * D_ + kc * 16 + 2 * c + 8);
        }
    }

    float oacc[16][4];
    #pragma unroll
    for (int t = 0; t < 16; t++) {
        oacc[t][0] = 0.f; oacc[t][1] = 0.f; oacc[t][2] = 0.f; oacc[t][3] = 0.f;
    }
    float m0 = -INFINITY, m1 = -INFINITY;
    float l0 = 0.f, l1 = 0.f;

    // ---- double-buffered KV tile loader (fp16, 256B rows) ----
    auto issue = [&](int stage, int kt) {
        const __half* Ks = Kh + (size_t)(kt * BN) * D_;
        const __half* Vs = Vh + (size_t)(kt * BN) * D_;
        #pragma unroll
        for (int i = 0; i < 8; i++) {
            int lin = tid + i * NTHREAD;          // 0..1023
            int row = lin >> 4;                    // 0..63
            int ch  = (lin & 15) * 16;             // byte 0..240
            cp16(smb + KOFFB(stage) + (uint32_t)(row * KPITCH_B + ch),
                 (const char*)(Ks + (size_t)row * D_) + ch);
            cp16(smb + VOFFB(stage) + (uint32_t)(row * KPITCH_B + ch),
                 (const char*)(Vs + (size_t)row * D_) + ch);
        }
        asm volatile("cp.async.commit_group;\n" ::: "memory");
    };

    issue(0, 0);

    for (int kt = 0; kt < niter; kt++) {
        const int cur = kt & 1;

        asm volatile("cp.async.wait_group 0;\n" ::: "memory");
        __syncthreads();   // tile ready; all warps past previous iter (WAR on other stage)

        if (kt + 1 < niter) issue(cur ^ 1, kt + 1);

        const uint32_t kBase = smb + KOFFB(cur) + kLaneOff;
        const uint32_t vBase = smb + VOFFB(cur) + vLaneOff;

        // ---- S = Q K^T  ([16q x 64k] per warp) ----
        float sacc[8][4];
        #pragma unroll
        for (int j = 0; j < 8; j++) {
            sacc[j][0] = 0.f; sacc[j][1] = 0.f; sacc[j][2] = 0.f; sacc[j][3] = 0.f;
        }
        #pragma unroll
        for (int kc = 0; kc < 8; kc++) {          // d chunks of 16
            #pragma unroll
            for (int p = 0; p < 4; p++) {          // key groups of 16
                uint32_t b0, b1, b2, b3;
                ldsm4(b0, b1, b2, b3,
                      kBase + (uint32_t)(p * 16 * KPITCH_B + kc * 32));
                mma16(sacc[2 * p],     qa[kc], b0, b1);
                mma16(sacc[2 * p + 1], qa[kc], b2, b3);
            }
        }

        // ---- tail-tile mask: compacted key index >= cnt is padding ----
        if (kt == niter - 1) {
            const int base = kt * BN + 2 * c;
            #pragma unroll
            for (int j = 0; j < 8; j++) {
                float a0 = (base + j * 8)     < cnt ? 0.f : -1e30f;
                float a1 = (base + j * 8 + 1) < cnt ? 0.f : -1e30f;
                sacc[j][0] += a0; sacc[j][2] += a0;
                sacc[j][1] += a1; sacc[j][3] += a1;
            }
        }

        // ---- online softmax (exp2 domain) ----
        float mx0 = -INFINITY, mx1 = -INFINITY;
        #pragma unroll
        for (int j = 0; j < 8; j++) {
            mx0 = fmaxf(mx0, fmaxf(sacc[j][0], sacc[j][1]));
            mx1 = fmaxf(mx1, fmaxf(sacc[j][2], sacc[j][3]));
        }
        mx0 = fmaxf(mx0, __shfl_xor_sync(0xffffffffu, mx0, 1));
        mx0 = fmaxf(mx0, __shfl_xor_sync(0xffffffffu, mx0, 2));
        mx1 = fmaxf(mx1, __shfl_xor_sync(0xffffffffu, mx1, 1));
        mx1 = fmaxf(mx1, __shfl_xor_sync(0xffffffffu, mx1, 2));

        float mn0 = fmaxf(m0, mx0), mn1 = fmaxf(m1, mx1);
        float al0 = exp2f(m0 - mn0), al1 = exp2f(m1 - mn1);
        m0 = mn0; m1 = mn1;

        // ---- P: subtract max (f32), pack half2, exp via ex2.approx.f16x2 ----
        uint32_t pa[4][4];
        #pragma unroll
        for (int j = 0; j < 8; j++) {
            uint32_t h01 = h2u(__floats2half2_rn(sacc[j][0] - mn0, sacc[j][1] - mn0));
            uint32_t h23 = h2u(__floats2half2_rn(sacc[j][2] - mn1, sacc[j][3] - mn1));
            pa[j >> 1][(j & 1) ? 2 : 0] = ex2h2(h01);
            pa[j >> 1][(j & 1) ? 3 : 1] = ex2h2(h23);
        }

        // ---- row sums of P via mma against all-ones B ----
        float lacc[4] = {0.f, 0.f, 0.f, 0.f};
        #pragma unroll
        for (int kc = 0; kc < 4; kc++)
            mma16(lacc, pa[kc], ONES_H2, ONES_H2);
        l0 = l0 * al0 + lacc[0];
        l1 = l1 * al1 + lacc[2];

        // ---- O rescale (warp-uniform skip when no row max moved) ----
        bool noresc = (al0 == 1.f) && (al1 == 1.f);
        if (!__all_sync(0xffffffffu, noresc)) {
            #pragma unroll
            for (int t = 0; t < 16; t++) {
                oacc[t][0] *= al0; oacc[t][1] *= al0;
                oacc[t][2] *= al1; oacc[t][3] *= al1;
            }
        }

        // ---- O += P V  (B via ldmatrix.trans on V[key][d]) ----
        #pragma unroll
        for (int kc = 0; kc < 4; kc++) {          // key chunks of 16
            #pragma unroll
            for (int dp = 0; dp < 8; dp++) {       // d pairs of 16
                uint32_t v0, v1, v2, v3;
                ldsm4t(v0, v1, v2, v3,
                       vBase + (uint32_t)(kc * 16 * KPITCH_B + dp * 32));
                mma16(oacc[2 * dp],     pa[kc], v0, v1);
                mma16(oacc[2 * dp + 1], pa[kc], v2, v3);
            }
        }
        // next iteration's top __syncthreads guards stage reuse
    }

    // ---- epilogue: normalize + store (f32) ----
    const float li0 = 1.f / l0;
    const float li1 = 1.f / l1;
    const int head = bh & 7;
    float* Op = out + ((size_t)batch * S_ + (size_t)qtile * BM + warp * 16) * UNITS_
              + head * D_;
    #pragma unroll
    for (int t = 0; t < 16; t++) {
        *(float2*)(Op + (size_t)r * UNITS_ + t * 8 + 2 * c) =
            make_float2(oacc[t][0] * li0, oacc[t][1] * li0);
        *(float2*)(Op + (size_t)(r + 8) * UNITS_ + t * 8 + 2 * c) =
            make_float2(oacc[t][2] * li1, oacc[t][3] * li1);
    }
}

extern "C" void kernel_launch(void* const* d_in, const int* in_sizes, int n_in,
                              void* d_out, int out_size)
{
    const float* memory = (const float*)d_in[0];
    const float* query  = (const float*)d_in[1];
    const int*   seqm   = (const int*)d_in[2];
    // d_in[3] (scalar bias b) is provably a no-op under softmax -> ignored.

    scan_kernel<<<B_, 1024>>>(seqm);
    convert_kernel<<<4096, 256>>>(memory, query, seqm);

    cudaFuncSetAttribute(attn_fa2_fp16_kernel,
                         cudaFuncAttributeMaxDynamicSharedMemorySize, SMEM_BYTES);
    dim3 grid(S_ / BM, B_ * H_);
    attn_fa2_fp16_kernel<<<grid, NTHREAD, SMEM_BYTES>>>((float*)d_out);
}

// round 17
// speedup vs baseline: 1.8954x; 1.0456x over previous
#include <cuda_runtime.h>
#include <cuda_fp16.h>
#include <cstdint>
#include <math.h>

// Attention_89627377533069 — FA2 fp16 mma.m16n8k16 + masked-key compaction.
// memory [8,1024,2048] f32 (K|V), query [8,1024,1024] f32, seq_mask [8,1024] i32, b [1] f32
// out [8,1024,1024] f32. Scalar bias b is softmax-shift-invariant -> ignored (exact).
//
// Masked keys (seq_mask==0, ~50%) contribute exactly 0 to the reference output
// (exp underflow vs -1e30), and softmax is invariant under a shared K/V permutation.
// The convert kernel recomputes the mask prefix-scan per block from 32 ballot words
// (mask is 32KB, L2-resident) — no separate scan kernel, no g_idx round trip.
// Q scaled by 1/sqrt(d)*log2(e); softmax in the exp2 domain; P row-sums via an
// extra mma against all-ones B; exp via ex2.approx.f16x2.

#define B_      8
#define S_      1024
#define H_      8
#define D_      128
#define UNITS_  1024
#define BM      64
#define BN      64
#define NTHREAD 128

// fp16 scratch, head-major [b*8+h][s][d]; K/V hold compacted keys.
__device__ __half g_Qh[B_ * H_ * S_ * D_];
__device__ __half g_Kh[B_ * H_ * S_ * D_];
__device__ __half g_Vh[B_ * H_ * S_ * D_];
__device__ int    g_cnt[B_];        // valid-key count per batch

// smem: K/V tiles [64 rows][136 halfs] (272B pitch; 272%128=16 -> conflict-free ldmatrix)
#define KPITCH_B  272
#define TILE_B    (BN * KPITCH_B)          // 17408
#define KOFFB(s)  ((uint32_t)(s) * TILE_B)              // 0, 17408
#define VOFFB(s)  (uint32_t)(2 * TILE_B + (s) * TILE_B) // 34816, 52224
#define SMEM_BYTES (4 * TILE_B)            // 69632 -> 2 CTAs/SM

#define ONES_H2 0x3C003C00u                 // half2(1.0, 1.0)

__device__ __forceinline__ uint32_t h2u(__half2 h) {
    union { __half2 h; uint32_t u; } cvt;
    cvt.h = h;
    return cvt.u;
}

__device__ __forceinline__ uint32_t ex2h2(uint32_t x) {
    uint32_t d;
    asm("ex2.approx.f16x2 %0, %1;" : "=r"(d) : "r"(x));
    return d;
}

__device__ __forceinline__ void mma16(float* c, const uint32_t* a, uint32_t b0, uint32_t b1) {
    asm volatile(
        "mma.sync.aligned.m16n8k16.row.col.f32.f16.f16.f32 "
        "{%0,%1,%2,%3}, {%4,%5,%6,%7}, {%8,%9}, {%0,%1,%2,%3};\n"
        : "+f"(c[0]), "+f"(c[1]), "+f"(c[2]), "+f"(c[3])
        : "r"(a[0]), "r"(a[1]), "r"(a[2]), "r"(a[3]), "r"(b0), "r"(b1));
}

__device__ __forceinline__ void ldsm4(uint32_t& r0, uint32_t& r1, uint32_t& r2, uint32_t& r3,
                                      uint32_t addr) {
    asm volatile("ldmatrix.sync.aligned.m8n8.x4.shared.b16 {%0,%1,%2,%3}, [%4];\n"
                 : "=r"(r0), "=r"(r1), "=r"(r2), "=r"(r3) : "r"(addr) : "memory");
}
__device__ __forceinline__ void ldsm4t(uint32_t& r0, uint32_t& r1, uint32_t& r2, uint32_t& r3,
                                       uint32_t addr) {
    asm volatile("ldmatrix.sync.aligned.m8n8.x4.trans.shared.b16 {%0,%1,%2,%3}, [%4];\n"
                 : "=r"(r0), "=r"(r1), "=r"(r2), "=r"(r3) : "r"(addr) : "memory");
}

__device__ __forceinline__ void cp16(uint32_t s, const void* g) {
    asm volatile("cp.async.ca.shared.global [%0], [%1], 16;\n" :: "r"(s), "l"(g));
}

// ---------------- convert kernel: scan + f32 -> fp16 scratch (compacted) ----------
// One block = one (batch, head, 16-key chunk); 256 threads = 16 keys x 16 d-chunks.
__global__ void __launch_bounds__(256, 4)
convert_kernel(const float* __restrict__ memory, const float* __restrict__ query,
               const int* __restrict__ seq_mask)
{
    const int tid = threadIdx.x;
    const int idx = blockIdx.x * 256 + tid;           // 0 .. 1048575
    const int d0 = (idx & 15) * 8;
    const int s  = (idx >> 4) & 1023;
    const int h  = (idx >> 14) & 7;
    const int b  = idx >> 17;
    // 1/sqrt(128) * log2(e): softmax evaluated with exp2
    const float scale = 0.08838834764831845f * 1.4426950408889634f;

    // ---- local mask scan: 32 ballot words for this batch ----
    __shared__ uint32_t words[32];
    {
        const int w = tid >> 5, lane = tid & 31;
        #pragma unroll
        for (int i = 0; i < 4; i++) {
            int word = w * 4 + i;
            unsigned bal = __ballot_sync(0xffffffffu,
                                         seq_mask[b * S_ + word * 32 + lane] != 0);
            if (lane == 0) words[word] = bal;
        }
    }
    __syncthreads();

    // ---- Q convert (always) ----
    {
        const float* qp = query + ((size_t)b * S_ + s) * UNITS_ + h * D_ + d0;
        float4 a0 = ((const float4*)qp)[0], a1 = ((const float4*)qp)[1];
        uint4 q;
        q.x = h2u(__floats2half2_rn(a0.x * scale, a0.y * scale));
        q.y = h2u(__floats2half2_rn(a0.z * scale, a0.w * scale));
        q.z = h2u(__floats2half2_rn(a1.x * scale, a1.y * scale));
        q.w = h2u(__floats2half2_rn(a1.z * scale, a1.w * scale));
        *(uint4*)(g_Qh + (((size_t)(b * 8 + h) * S_) + s) * D_ + d0) = q;
    }

    // ---- prefix + count from ballot words ----
    const int sw = s >> 5;
    int pre = 0;
    for (int i = 0; i < sw; i++) pre += __popc(words[i]);
    pre += __popc(words[sw] & ((1u << (s & 31)) - 1u));
    const bool valid = (words[sw] >> (s & 31)) & 1u;

    int cnt = 0;
    #pragma unroll
    for (int i = 0; i < 32; i++) cnt += __popc(words[i]);
    if (h == 0 && s == 0 && d0 == 0) g_cnt[b] = cnt;   // one thread per batch

    int row;
    if (valid) {
        row = pre;                                      // compacted destination
    } else {
        const int pad = (cnt + 63) & ~63;
        const int iidx = s - pre;                       // invalid keys before s
        row = cnt + iidx;
        if (row >= pad) return;                         // only fill [cnt, pad)
    }

    const size_t dst = (((size_t)(b * 8 + h) * S_) + row) * D_ + d0;
    if (!valid) {
        uint4 z = make_uint4(0, 0, 0, 0);
        *(uint4*)(g_Kh + dst) = z;
        *(uint4*)(g_Vh + dst) = z;
        return;
    }

    const float* kp = memory + ((size_t)b * S_ + s) * 2048 + h * D_ + d0;
    const float* vp = kp + UNITS_;
    float4 a0 = ((const float4*)kp)[0], a1 = ((const float4*)kp)[1];
    uint4 q;
    q.x = h2u(__floats2half2_rn(a0.x, a0.y));
    q.y = h2u(__floats2half2_rn(a0.z, a0.w));
    q.z = h2u(__floats2half2_rn(a1.x, a1.y));
    q.w = h2u(__floats2half2_rn(a1.z, a1.w));
    *(uint4*)(g_Kh + dst) = q;

    a0 = ((const float4*)vp)[0]; a1 = ((const float4*)vp)[1];
    q.x = h2u(__floats2half2_rn(a0.x, a0.y));
    q.y = h2u(__floats2half2_rn(a0.z, a0.w));
    q.z = h2u(__floats2half2_rn(a1.x, a1.y));
    q.w = h2u(__floats2half2_rn(a1.z, a1.w));
    *(uint4*)(g_Vh + dst) = q;
}

// ---------------- attention kernel ----------------
__global__ void __launch_bounds__(NTHREAD, 2)
attn_fa2_fp16_kernel(float* __restrict__ out)
{
    extern __shared__ char smem[];
    const int tid  = threadIdx.x;
    const int warp = tid >> 5;
    const int lane = tid & 31;
    const int r = lane >> 2;    // fragment row group
    const int c = lane & 3;     // thread-in-group
    const int qtile = blockIdx.x;
    const int bh    = blockIdx.y;           // b*8 + h
    const int batch = bh >> 3;

    const __half* Kh = g_Kh + (size_t)bh * S_ * D_;
    const __half* Vh = g_Vh + (size_t)bh * S_ * D_;
    const int cnt = g_cnt[batch];
    const int niter = (cnt + BN - 1) >> 6;   // tiles of 64 compacted keys

    const uint32_t smb = (uint32_t)__cvta_generic_to_shared(smem);

    // ---- ldmatrix per-lane address components ----
    const int kRow = (lane & 7) + ((lane >> 4) << 3);        // key 0..15
    const int kColH = ((lane >> 3) & 1) << 3;                // d 0 or 8 (halfs)
    const uint32_t kLaneOff = (uint32_t)(kRow * KPITCH_B + kColH * 2);
    const int vRow = (lane & 7) + (((lane >> 3) & 1) << 3);  // key 0..15
    const int vColH = (lane >> 4) << 3;                      // d 0 or 8 (halfs)
    const uint32_t vLaneOff = (uint32_t)(vRow * KPITCH_B + vColH * 2);

    // ---- Q A-fragments in registers (pre-scaled fp16 from scratch) ----
    uint32_t qa[8][4];
    {
        const __half* Qp = g_Qh + ((size_t)bh * S_ + qtile * BM + warp * 16) * D_;
        #pragma unroll
        for (int kc = 0; kc < 8; kc++) {
            qa[kc][0] = *(const uint32_t*)(Qp + (size_t)r * D_       + kc * 16 + 2 * c);
            qa[kc][1] = *(const uint32_t*)(Qp + (size_t)(r + 8) * D_ + kc * 16 + 2 * c);
            qa[kc][2] = *(const uint32_t*)(Qp + (size_t)r * D_       + kc * 16 + 2 * c + 8);
            qa[kc][3] = *(const uint32_t*)(Qp + (size_t)(r + 8) * D_ + kc * 16 + 2 * c + 8);
        }
    }

    float oacc[16][4];
    #pragma unroll
    for (int t = 0; t < 16; t++) {
        oacc[t][0] = 0.f; oacc[t][1] = 0.f; oacc[t][2] = 0.f; oacc[t][3] = 0.f;
    }
    float m0 = -INFINITY, m1 = -INFINITY;
    float l0 = 0.f, l1 = 0.f;

    // ---- double-buffered KV tile loader (fp16, 256B rows) ----
    auto issue = [&](int stage, int kt) {
        const __half* Ks = Kh + (size_t)(kt * BN) * D_;
        const __half* Vs = Vh + (size_t)(kt * BN) * D_;
        #pragma unroll
        for (int i = 0; i < 8; i++) {
            int lin = tid + i * NTHREAD;          // 0..1023
            int row = lin >> 4;                    // 0..63
            int ch  = (lin & 15) * 16;             // byte 0..240
            cp16(smb + KOFFB(stage) + (uint32_t)(row * KPITCH_B + ch),
                 (const char*)(Ks + (size_t)row * D_) + ch);
            cp16(smb + VOFFB(stage) + (uint32_t)(row * KPITCH_B + ch),
                 (const char*)(Vs + (size_t)row * D_) + ch);
        }
        asm volatile("cp.async.commit_group;\n" ::: "memory");
    };

    issue(0, 0);

    for (int kt = 0; kt < niter; kt++) {
        const int cur = kt & 1;

        asm volatile("cp.async.wait_group 0;\n" ::: "memory");
        __syncthreads();   // tile ready; all warps past previous iter (WAR on other stage)

        if (kt + 1 < niter) issue(cur ^ 1, kt + 1);

        const uint32_t kBase = smb + KOFFB(cur) + kLaneOff;
        const uint32_t vBase = smb + VOFFB(cur) + vLaneOff;

        // ---- S = Q K^T  ([16q x 64k] per warp) ----
        float sacc[8][4];
        #pragma unroll
        for (int j = 0; j < 8; j++) {
            sacc[j][0] = 0.f; sacc[j][1] = 0.f; sacc[j][2] = 0.f; sacc[j][3] = 0.f;
        }
        #pragma unroll
        for (int kc = 0; kc < 8; kc++) {          // d chunks of 16
            #pragma unroll
            for (int p = 0; p < 4; p++) {          // key groups of 16
                uint32_t b0, b1, b2, b3;
                ldsm4(b0, b1, b2, b3,
                      kBase + (uint32_t)(p * 16 * KPITCH_B + kc * 32));
                mma16(sacc[2 * p],     qa[kc], b0, b1);
                mma16(sacc[2 * p + 1], qa[kc], b2, b3);
            }
        }

        // ---- tail-tile mask: compacted key index >= cnt is padding ----
        if (kt == niter - 1) {
            const int base = kt * BN + 2 * c;
            #pragma unroll
            for (int j = 0; j < 8; j++) {
                float a0 = (base + j * 8)     < cnt ? 0.f : -1e30f;
                float a1 = (base + j * 8 + 1) < cnt ? 0.f : -1e30f;
                sacc[j][0] += a0; sacc[j][2] += a0;
                sacc[j][1] += a1; sacc[j][3] += a1;
            }
        }

        // ---- online softmax (exp2 domain) ----
        float mx0 = -INFINITY, mx1 = -INFINITY;
        #pragma unroll
        for (int j = 0; j < 8; j++) {
            mx0 = fmaxf(mx0, fmaxf(sacc[j][0], sacc[j][1]));
            mx1 = fmaxf(mx1, fmaxf(sacc[j][2], sacc[j][3]));
        }
        mx0 = fmaxf(mx0, __shfl_xor_sync(0xffffffffu, mx0, 1));
        mx0 = fmaxf(mx0, __shfl_xor_sync(0xffffffffu, mx0, 2));
        mx1 = fmaxf(mx1, __shfl_xor_sync(0xffffffffu, mx1, 1));
        mx1 = fmaxf(mx1, __shfl_xor_sync(0xffffffffu, mx1, 2));

        float mn0 = fmaxf(m0, mx0), mn1 = fmaxf(m1, mx1);
        float al0 = exp2f(m0 - mn0), al1 = exp2f(m1 - mn1);
        m0 = mn0; m1 = mn1;

        // ---- P: subtract max (f32), pack half2, exp via ex2.approx.f16x2 ----
        uint32_t pa[4][4];
        #pragma unroll
        for (int j = 0; j < 8; j++) {
            uint32_t h01 = h2u(__floats2half2_rn(sacc[j][0] - mn0, sacc[j][1] - mn0));
            uint32_t h23 = h2u(__floats2half2_rn(sacc[j][2] - mn1, sacc[j][3] - mn1));
            pa[j >> 1][(j & 1) ? 2 : 0] = ex2h2(h01);
            pa[j >> 1][(j & 1) ? 3 : 1] = ex2h2(h23);
        }

        // ---- row sums of P via mma against all-ones B ----
        float lacc[4] = {0.f, 0.f, 0.f, 0.f};
        #pragma unroll
        for (int kc = 0; kc < 4; kc++)
            mma16(lacc, pa[kc], ONES_H2, ONES_H2);
        l0 = l0 * al0 + lacc[0];
        l1 = l1 * al1 + lacc[2];

        // ---- O rescale (warp-uniform skip when no row max moved) ----
        bool noresc = (al0 == 1.f) && (al1 == 1.f);
        if (!__all_sync(0xffffffffu, noresc)) {
            #pragma unroll
            for (int t = 0; t < 16; t++) {
                oacc[t][0] *= al0; oacc[t][1] *= al0;
                oacc[t][2] *= al1; oacc[t][3] *= al1;
            }
        }

        // ---- O += P V  (B via ldmatrix.trans on V[key][d]) ----
        #pragma unroll
        for (int kc = 0; kc < 4; kc++) {          // key chunks of 16
            #pragma unroll
            for (int dp = 0; dp < 8; dp++) {       // d pairs of 16
                uint32_t v0, v1, v2, v3;
                ldsm4t(v0, v1, v2, v3,
                       vBase + (uint32_t)(kc * 16 * KPITCH_B + dp * 32));
                mma16(oacc[2 * dp],     pa[kc], v0, v1);
                mma16(oacc[2 * dp + 1], pa[kc], v2, v3);
            }
        }
        // next iteration's top __syncthreads guards stage reuse
    }

    // ---- epilogue: normalize + store (f32) ----
    const float li0 = 1.f / l0;
    const float li1 = 1.f / l1;
    const int head = bh & 7;
    float* Op = out + ((size_t)batch * S_ + (size_t)qtile * BM + warp * 16) * UNITS_
              + head * D_;
    #pragma unroll
    for (int t = 0; t < 16; t++) {
        *(float2*)(Op + (size_t)r * UNITS_ + t * 8 + 2 * c) =
            make_float2(oacc[t][0] * li0, oacc[t][1] * li0);
        *(float2*)(Op + (size_t)(r + 8) * UNITS_ + t * 8 + 2 * c) =
            make_float2(oacc[t][2] * li1, oacc[t][3] * li1);
    }
}

extern "C" void kernel_launch(void* const* d_in, const int* in_sizes, int n_in,
                              void* d_out, int out_size)
{
    const float* memory = (const float*)d_in[0];
    const float* query  = (const float*)d_in[1];
    const int*   seqm   = (const int*)d_in[2];
    // d_in[3] (scalar bias b) is provably a no-op under softmax -> ignored.

    convert_kernel<<<4096, 256>>>(memory, query, seqm);

    cudaFuncSetAttribute(attn_fa2_fp16_kernel,
                         cudaFuncAttributeMaxDynamicSharedMemorySize, SMEM_BYTES);
    dim3 grid(S_ / BM, B_ * H_);
    attn_fa2_fp16_kernel<<<grid, NTHREAD, SMEM_BYTES>>>((float*)d_out);
}